// round 14
// baseline (speedup 1.0000x reference)
#include <cuda_runtime.h>
#include <cuda_fp16.h>
#include <math.h>
#include <stdint.h>

#define U   1024
#define Bsz 64
#define T   128
#define Dd  256
#define N5  (5*U)        // 5120
#define N3  (3*U)        // 3072
#define KTOT (Dd + 2*U)  // 2304

#define NCTA   148                 // == B300 SM count; all co-resident (1 CTA/SM)
#define NTILE  128
#define KCH    64                  // K elems per chunk
#define ZCPT   36                  // z chunks per tile (2304/64)
#define ZCHUNKS 1440               // 40 tiles * 36
#define FCPT   48                  // agg chunks per tile (3072/64)
#define AGG_CTAS 128               // 128 CTAs * 3 chunks = 384 = 8 tiles * 48

// SMEM: rows padded to 144B -> conflict-free ldmatrix
#define ROWB   144
#define A_BLK  (64 * ROWB)             // 9216
#define B_BLK  (128 * ROWB)            // 18432
#define STG_BYTES (A_BLK + B_BLK)      // 27648
#define NSTG   4
#define GSMEM_BYTES (NSTG * STG_BYTES) // 110592

#define Z4T (Bsz * N5 / 4)             // 81920 float4
#define F4T (Bsz * U  / 4)             // 16384 float4

// ---------------- static device scratch --------------------------------------
__device__ __align__(128) __half g_Wt [(size_t)N5 * KTOT];  // W^T fp16 [n][k]
__device__ __align__(128) __half g_AGt[(size_t)U * N3];     // agg^T fp16 [n][k]
__device__ __align__(128) __half g_A16[Bsz * KTOT];         // [x|h|c] fp16
__device__ __align__(128) __half g_O16[Bsz * N3];           // O fp16
__device__ __align__(128) float g_c  [Bsz * U];
__device__ __align__(128) float g_z  [2][Bsz * N5];         // summed z (atomic acc)
__device__ __align__(128) float g_f  [2][Bsz * U];          // summed f (atomic acc)
__device__ float g_s[6];
__device__ unsigned g_barA[T];
__device__ unsigned g_barB[T];
__device__ unsigned g_barC[T];
__device__ unsigned g_barD[T];

// ---------------- helpers -----------------------------------------------------
__device__ __forceinline__ float sigf(float x) { return 1.f / (1.f + expf(-x)); }

__device__ __forceinline__ uint32_t smem_u32(const void* p) {
    uint32_t a;
    asm("{ .reg .u64 t; cvta.to.shared.u64 t, %1; cvt.u32.u64 %0, t; }" : "=r"(a) : "l"(p));
    return a;
}
__device__ __forceinline__ void cpasync16(uint32_t s, const void* g) {
    asm volatile("cp.async.cg.shared.global [%0], [%1], 16;" :: "r"(s), "l"(g) : "memory");
}
__device__ __forceinline__ void cp_commit() { asm volatile("cp.async.commit_group;" ::: "memory"); }
template<int N> __device__ __forceinline__ void cp_wait() {
    asm volatile("cp.async.wait_group %0;" :: "n"(N) : "memory");
}
__device__ __forceinline__ void ldsm4(uint32_t* d, uint32_t addr) {
    asm volatile("ldmatrix.sync.aligned.m8n8.x4.shared.b16 {%0,%1,%2,%3}, [%4];"
                 : "=r"(d[0]), "=r"(d[1]), "=r"(d[2]), "=r"(d[3]) : "r"(addr));
}
__device__ __forceinline__ void mma16816(float* c, const uint32_t* a, const uint32_t* b) {
    asm volatile("mma.sync.aligned.m16n8k16.row.col.f32.f16.f16.f32 "
                 "{%0,%1,%2,%3}, {%4,%5,%6,%7}, {%8,%9}, {%0,%1,%2,%3};"
                 : "+f"(c[0]), "+f"(c[1]), "+f"(c[2]), "+f"(c[3])
                 : "r"(a[0]), "r"(a[1]), "r"(a[2]), "r"(a[3]), "r"(b[0]), "r"(b[1]));
}
__device__ __forceinline__ void red_release_add(unsigned* p, unsigned v) {
    asm volatile("red.release.gpu.global.add.u32 [%0], %1;" :: "l"(p), "r"(v) : "memory");
}
__device__ __forceinline__ unsigned ld_acquire(const unsigned* p) {
    unsigned v;
    asm volatile("ld.acquire.gpu.global.u32 %0, [%1];" : "=r"(v) : "l"(p) : "memory");
    return v;
}
__device__ __forceinline__ void red_addf(float* p, float v) {
    asm volatile("red.global.add.f32 [%0], %1;" :: "l"(p), "f"(v) : "memory");
}
__device__ __forceinline__ float4 ldcg4(const float* p) {
    float4 v;
    asm volatile("ld.global.cg.v4.f32 {%0,%1,%2,%3}, [%4];"
                 : "=f"(v.x), "=f"(v.y), "=f"(v.z), "=f"(v.w) : "l"(p));
    return v;
}
__device__ __forceinline__ void gbarN(unsigned* ctr, int tid, unsigned target) {
    __syncthreads();
    if (tid == 0) {
        red_release_add(ctr, 1u);
        while (ld_acquire(ctr) < target) __nanosleep(32);
    }
    __syncthreads();
}

// ---------------- block reduce helpers ----------------------------------------
__device__ __forceinline__ float blk_reduce_max(float v, float* sm) {
    #pragma unroll
    for (int o = 16; o; o >>= 1) v = fmaxf(v, __shfl_xor_sync(0xffffffffu, v, o));
    int w = threadIdx.x >> 5;
    if ((threadIdx.x & 31) == 0) sm[w] = v;
    __syncthreads();
    float r = sm[0];
    #pragma unroll
    for (int i = 1; i < 8; i++) r = fmaxf(r, sm[i]);
    __syncthreads();
    return r;
}
__device__ __forceinline__ float blk_reduce_sum(float v, float* sm) {
    #pragma unroll
    for (int o = 16; o; o >>= 1) v += __shfl_xor_sync(0xffffffffu, v, o);
    int w = threadIdx.x >> 5;
    if ((threadIdx.x & 31) == 0) sm[w] = v;
    __syncthreads();
    float r = sm[0];
    #pragma unroll
    for (int i = 1; i < 8; i++) r += sm[i];
    __syncthreads();
    return r;
}
struct ScanRes { float excl; float total; };
__device__ __forceinline__ ScanRes blk_scan(float s, float* sm) {
    float ws = s;
    #pragma unroll
    for (int o = 1; o < 32; o <<= 1) {
        float t = __shfl_up_sync(0xffffffffu, ws, o);
        if ((threadIdx.x & 31) >= o) ws += t;
    }
    int w = threadIdx.x >> 5;
    if ((threadIdx.x & 31) == 31) sm[w] = ws;
    __syncthreads();
    float warpBase = 0.f, run = 0.f;
    #pragma unroll
    for (int i = 0; i < 8; i++) { float t = sm[i]; if (i == w) warpBase = run; run += t; }
    __syncthreads();
    ScanRes r; r.excl = warpBase + (ws - s); r.total = run; return r;
}

// ---------------- init kernels -------------------------------------------------
__global__ void ktrans_W(const float* __restrict__ k1, const float* __restrict__ k2,
                         const float* __restrict__ k3) {
    __shared__ float tile[32][33];
    int kt = blockIdx.x * 32, nt = blockIdx.y * 32;
    int tx = threadIdx.x, ty = threadIdx.y;
    #pragma unroll
    for (int i = 0; i < 32; i += 8) {
        int k = kt + ty + i, n = nt + tx;
        const float* src; int kr;
        if (k < Dd) { src = k1; kr = k; }
        else if (k < Dd + U) { src = k2; kr = k - Dd; }
        else { src = k3; kr = k - Dd - U; }
        tile[ty + i][tx] = src[(size_t)kr * N5 + n];
    }
    __syncthreads();
    #pragma unroll
    for (int i = 0; i < 32; i += 8) {
        int n = nt + ty + i, k = kt + tx;
        g_Wt[(size_t)n * KTOT + k] = __float2half(tile[tx][ty + i]);
    }
}
__global__ void ktrans_AG(const float* __restrict__ agg) {
    __shared__ float tile[32][33];
    int kt = blockIdx.x * 32, nt = blockIdx.y * 32;
    int tx = threadIdx.x, ty = threadIdx.y;
    #pragma unroll
    for (int i = 0; i < 32; i += 8)
        tile[ty + i][tx] = agg[(size_t)(kt + ty + i) * U + nt + tx];
    __syncthreads();
    #pragma unroll
    for (int i = 0; i < 32; i += 8) {
        int n = nt + ty + i, k = kt + tx;
        g_AGt[(size_t)n * N3 + k] = __float2half(tile[tx][ty + i]);
    }
}

// one merged init kernel: scalars + A/c init + counters + g_z[0]/g_f[0] zero
__global__ void kinit_all(const float* __restrict__ x,
                          const float* a0, const float* b0, const float* a1, const float* b1,
                          const float* a2, const float* b2, const float* a3, const float* b3,
                          const float* a4, const float* b4, const float* a5, const float* b5) {
    __shared__ float sm[8];
    int b = blockIdx.x;
    if (b == 0) {
        const float* as[6] = {a0, a1, a2, a3, a4, a5};
        const float* bs[6] = {b0, b1, b2, b3, b4, b5};
        for (int p = 0; p < 6; p++) {
            float s = 0.f;
            for (int i = threadIdx.x; i < U; i += 256) s += as[p][i] * bs[p][i];
            float tot = blk_reduce_sum(s, sm);
            if (threadIdx.x == 0) g_s[p] = tot;
            __syncthreads();
        }
        if (threadIdx.x < T) {
            g_barA[threadIdx.x] = 0u;
            g_barB[threadIdx.x] = 0u;
            g_barC[threadIdx.x] = 0u;
            g_barD[threadIdx.x] = 0u;
        }
    }
    for (int i = threadIdx.x; i < KTOT; i += 256)
        g_A16[b * KTOT + i] = __float2half((i < Dd) ? x[(size_t)(b * T) * Dd + i] : 0.f);
    for (int i = threadIdx.x; i < U; i += 256) g_c[b * U + i] = 0.f;
    // zero g_z[0], g_f[0] across 64 blocks
    float4 z4 = make_float4(0.f, 0.f, 0.f, 0.f);
    for (int i = b * 256 + threadIdx.x; i < Z4T + F4T; i += 64 * 256) {
        if (i < Z4T) reinterpret_cast<float4*>(g_z[0])[i] = z4;
        else         reinterpret_cast<float4*>(g_f[0])[i - Z4T] = z4;
    }
}

// ---------------- chunk-range GEMM with atomic-add epilogue ---------------------
// MODE 0: z (A=g_A16 LDK=2304, W=g_Wt, CPT=36) | MODE 1: f (A=g_O16 LDK=3072, W=g_AGt, CPT=48)
template<int MODE>
__device__ __forceinline__ void gemm_range(uint32_t smb, int tid, int start, int cnt,
                                           float* __restrict__ OUT) {
    constexpr int LDK  = (MODE == 0) ? KTOT : N3;
    constexpr int NTOT = (MODE == 0) ? N5 : U;
    constexpr int CPT  = (MODE == 0) ? ZCPT : FCPT;

    const __half* Wp = (MODE == 0) ? g_Wt : g_AGt;
    const __half* Ap = (MODE == 0) ? g_A16 : g_O16;

    const int lane = tid & 31;
    const int w    = tid >> 5;

    int   roff[6];
    uint32_t dstO[6];
    bool  isA_[6];
    #pragma unroll
    for (int i = 0; i < 6; i++) {
        int seg = tid + i * 256;
        if (seg < 512) {
            int r = seg >> 3, s = seg & 7;
            roff[i] = r * LDK + s * 8;
            dstO[i] = r * ROWB + s * 16;
            isA_[i] = true;
        } else {
            int idx = seg - 512;
            int r = idx >> 3, s = idx & 7;
            roff[i] = r * LDK + s * 8;
            dstO[i] = A_BLK + r * ROWB + s * 16;
            isA_[i] = false;
        }
    }
    auto load_chunk = [&](int cid, int stg) {
        const int n0 = (cid / CPT) * NTILE;
        const int kk = (cid % CPT) * KCH;
        const __half* ab = Ap + kk;
        const __half* wb = Wp + (size_t)n0 * LDK + kk;
        const uint32_t bb = smb + stg * STG_BYTES;
        #pragma unroll
        for (int i = 0; i < 6; i++)
            cpasync16(bb + dstO[i], (isA_[i] ? ab : wb) + roff[i]);
        cp_commit();
    };

    const int mrow0 = (w & 1) * 32;
    const int nrow0 = (w >> 1) * 32;
    const int rA  = mrow0 + (lane & 15);
    const int scA = lane >> 4;
    const int rB  = nrow0 + ((lane >> 4) << 3) + (lane & 7);
    const int scB = (lane >> 3) & 1;

    float acc[2][4][4] = {};

    auto flush = [&](int n0) {
        #pragma unroll
        for (int mi = 0; mi < 2; mi++) {
            #pragma unroll
            for (int nf = 0; nf < 4; nf++) {
                int row = mrow0 + mi * 16 + (lane >> 2);
                int col = n0 + nrow0 + nf * 8 + (lane & 3) * 2;
                red_addf(OUT + (size_t)row * NTOT + col,       acc[mi][nf][0]);
                red_addf(OUT + (size_t)row * NTOT + col + 1,   acc[mi][nf][1]);
                red_addf(OUT + (size_t)(row + 8) * NTOT + col,     acc[mi][nf][2]);
                red_addf(OUT + (size_t)(row + 8) * NTOT + col + 1, acc[mi][nf][3]);
                acc[mi][nf][0] = acc[mi][nf][1] = acc[mi][nf][2] = acc[mi][nf][3] = 0.f;
            }
        }
    };

    #pragma unroll
    for (int p = 0; p < 3; p++)
        if (p < cnt) load_chunk(start + p, p);

    for (int c = 0; c < cnt; c++) {
        int rem = cnt - 1 - c;
        if (rem >= 2) cp_wait<2>(); else if (rem == 1) cp_wait<1>(); else cp_wait<0>();
        __syncthreads();
        if (c + 3 < cnt) load_chunk(start + c + 3, (c + 3) % NSTG);

        const uint32_t bb = smb + (c % NSTG) * STG_BYTES;
        #pragma unroll
        for (int s16 = 0; s16 < 4; s16++) {
            const int kd = s16 * 2;
            uint32_t ah[2][4], bh[2][4];
            #pragma unroll
            for (int mi = 0; mi < 2; mi++)
                ldsm4(ah[mi], bb + (rA + mi * 16) * ROWB + (kd + scA) * 16);
            #pragma unroll
            for (int nj = 0; nj < 2; nj++)
                ldsm4(bh[nj], bb + A_BLK + (rB + nj * 16) * ROWB + (kd + scB) * 16);
            #pragma unroll
            for (int mi = 0; mi < 2; mi++)
                #pragma unroll
                for (int nf = 0; nf < 4; nf++)
                    mma16816(acc[mi][nf], ah[mi], &bh[nf >> 1][(nf & 1) * 2]);
        }
        const int cid = start + c;
        if (c == cnt - 1 || (cid + 1) % CPT == 0)
            flush((cid / CPT) * NTILE);
    }
}

// ---------------- gate body (single summed z buffer + bias) --------------------
__device__ __forceinline__ void gate_body(int b, int tid, const float* __restrict__ zbuf,
                                          const float* __restrict__ bias) {
    __shared__ float sm[16];
    const int i0 = tid * 4;
    const float* zb = zbuf + (size_t)b * N5;

    float uz[4], dz[4], rz[4];
    {
        #define LOADB(off, out) {                                                   \
            float4 s0 = ldcg4(zb + (off));                                            \
            float4 bb = *reinterpret_cast<const float4*>(bias + (off));               \
            out[0] = s0.x + bb.x; out[1] = s0.y + bb.y;                               \
            out[2] = s0.z + bb.z; out[3] = s0.w + bb.w; }
        LOADB(i0,         uz)
        LOADB(U + i0,     dz)
        LOADB(2 * U + i0, rz)
        #undef LOADB
    }

    float mx = fmaxf(fmaxf(uz[0], uz[1]), fmaxf(uz[2], uz[3]));
    mx = blk_reduce_max(mx, sm);
    float e[4], ls = 0.f;
    #pragma unroll
    for (int l = 0; l < 4; l++) { e[l] = expf(uz[l] - mx); ls += e[l]; }
    ScanRes s1 = blk_scan(ls, sm);
    float up[4];
    { float P = s1.excl, inv = 1.f / s1.total;
      #pragma unroll
      for (int l = 0; l < 4; l++) { P += e[l]; up[l] = P * inv; } }

    float mx2 = fmaxf(fmaxf(dz[0], dz[1]), fmaxf(dz[2], dz[3]));
    mx2 = blk_reduce_max(mx2, sm);
    float ed[4]; ls = 0.f;
    #pragma unroll
    for (int l = 0; l < 4; l++) { ed[l] = expf(dz[l] - mx2); ls += ed[l]; }
    ScanRes s2 = blk_scan(ls, sm);
    float dn[4];
    { float P = s2.excl, inv = 1.f / s2.total;
      #pragma unroll
      for (int l = 0; l < 4; l++) { P += ed[l]; dn[l] = (s2.total - P + ed[l]) * inv; } }

    float pdu = 0.f, pru = 0.f, pdr = 0.f;
    #pragma unroll
    for (int l = 0; l < 4; l++) { pdu += dn[l] * up[l]; pru += rz[l] * up[l]; pdr += dn[l] * rz[l]; }
    float du = blk_reduce_sum(pdu, sm);
    float ru = blk_reduce_sum(pru, sm);
    float dr = blk_reduce_sum(pdr, sm);

    const float s_ud = g_s[0], s_ur = g_s[1], s_ru = g_s[2];
    const float s_rd = g_s[3], s_du = g_s[4], s_dr = g_s[5];

    #pragma unroll
    for (int l = 0; l < 4; l++) {
        float t1 = sigf(s_ud * up[l] * du) + sigf(s_ur * up[l] * ru);
        float t2 = sigf(s_ru * rz[l] * ru) + sigf(s_rd * rz[l] * dr);
        float t3 = sigf(s_du * dn[l] * du) + sigf(s_dr * dn[l] * dr);
        g_O16[b * N3 + i0 + l]         = __float2half(t1);
        g_O16[b * N3 + U + i0 + l]     = __float2half(t2);
        g_O16[b * N3 + 2 * U + i0 + l] = __float2half(t3);
    }
}

// ---------------- update body (single summed buffers + bias) -------------------
__device__ __forceinline__ void update_body(int b, int tid, int t,
                                            const float* __restrict__ zbuf,
                                            const float* __restrict__ fbuf,
                                            const float* __restrict__ x,
                                            const float* __restrict__ bias,
                                            float* __restrict__ out) {
    const int j = tid * 4;
    const float* zb = zbuf + (size_t)b * N5;

    float4 fs = ldcg4(fbuf + (size_t)b * U + j);
    float4 og = ldcg4(zb + 3 * U + j);
    float4 zc = ldcg4(zb + 4 * U + j);
    float4 bo = *reinterpret_cast<const float4*>(bias + 3 * U + j);
    float4 bc = *reinterpret_cast<const float4*>(bias + 4 * U + j);
    og.x += bo.x; og.y += bo.y; og.z += bo.z; og.w += bo.w;
    zc.x += bc.x; zc.y += bc.y; zc.z += bc.z; zc.w += bc.w;

    float fv[4] = {fs.x, fs.y, fs.z, fs.w};
    float ov[4] = {og.x, og.y, og.z, og.w};
    float zv[4] = {zc.x, zc.y, zc.z, zc.w};
    #pragma unroll
    for (int l = 0; l < 4; l++) {
        float f  = sigf(fv[l]);
        float ci = tanhf(zv[l]);
        float co = g_c[(size_t)b * U + j + l];
        float cn = f * co + (1.f - f) * ci;
        float hn = ov[l] * tanhf(cn);
        g_c[(size_t)b * U + j + l] = cn;
        out[((size_t)b * T + t) * U + j + l] = hn;
        g_A16[b * KTOT + Dd + j + l]     = __float2half(hn);
        g_A16[b * KTOT + Dd + U + j + l] = __float2half(cn);
    }
    if (t + 1 < T && tid < 64) {
        #pragma unroll
        for (int l = 0; l < 4; l++) {
            int d = tid * 4 + l;
            g_A16[b * KTOT + d] = __float2half(x[((size_t)b * T + (t + 1)) * Dd + d]);
        }
    }
}

// ---------------- persistent scan kernel: 148 CTAs, whole T loop ----------------
__global__ void __launch_bounds__(256) k_scan(const float* __restrict__ bias,
                                              const float* __restrict__ x,
                                              float* __restrict__ out) {
    const int bid = blockIdx.x, tid = threadIdx.x;
    extern __shared__ char dyn[];
    const uint32_t smb = smem_u32(dyn);

    int startz, cntz;
    if (bid < 108) { startz = bid * 10; cntz = 10; }
    else           { startz = 1080 + (bid - 108) * 9; cntz = 9; }

    for (int t = 0; t < T; t++) {
        const int cur = t & 1, nxt = (t + 1) & 1;

        // phase 1: z-GEMM chunks on all 148 CTAs, atomic-acc into g_z[cur]
        gemm_range<0>(smb, tid, startz, cntz, g_z[cur]);
        gbarN(&g_barA[t], tid, NCTA);

        // phase 2: gates on 0..63 | zero next-step buffers on 64..147
        if (bid < Bsz) {
            gate_body(bid, tid, g_z[cur], bias);
        } else {
            float4 z4 = make_float4(0.f, 0.f, 0.f, 0.f);
            for (int i = (bid - 64) * 256 + tid; i < Z4T + F4T; i += 84 * 256) {
                if (i < Z4T) reinterpret_cast<float4*>(g_z[nxt])[i] = z4;
                else         reinterpret_cast<float4*>(g_f[nxt])[i - Z4T] = z4;
            }
        }

        if (bid < AGG_CTAS) {
            gbarN(&g_barB[t], tid, AGG_CTAS);
            // phase 3: agg-GEMM, 128 CTAs x 3 chunks (single tile each)
            gemm_range<1>(smb, tid, bid * 3, 3, g_f[cur]);
            gbarN(&g_barC[t], tid, AGG_CTAS);
            // phase 4: update on 0..63
            if (bid < Bsz) update_body(bid, tid, t, g_z[cur], g_f[cur], x, bias, out);
        }
        gbarN(&g_barD[t], tid, NCTA);
    }
}

// ---------------- launch ---------------------------------------------------------
extern "C" void kernel_launch(void* const* d_in, const int* in_sizes, int n_in,
                              void* d_out, int out_size) {
    const float* x    = (const float*)d_in[0];
    const float* kern = (const float*)d_in[1];
    const float* rker = (const float*)d_in[2];
    const float* cker = (const float*)d_in[3];
    const float* bias = (const float*)d_in[4];
    const float* agg  = (const float*)d_in[5];
    float* out = (float*)d_out;

    cudaFuncSetAttribute(k_scan, cudaFuncAttributeMaxDynamicSharedMemorySize, GSMEM_BYTES);

    ktrans_W <<<dim3(KTOT / 32, N5 / 32), dim3(32, 8)>>>(kern, rker, cker);
    ktrans_AG<<<dim3(N3 / 32,  U  / 32), dim3(32, 8)>>>(agg);
    kinit_all<<<Bsz, 256>>>(x,
                            (const float*)d_in[6],  (const float*)d_in[7],
                            (const float*)d_in[8],  (const float*)d_in[9],
                            (const float*)d_in[10], (const float*)d_in[11],
                            (const float*)d_in[12], (const float*)d_in[13],
                            (const float*)d_in[14], (const float*)d_in[15],
                            (const float*)d_in[16], (const float*)d_in[17]);

    k_scan<<<NCTA, 256, GSMEM_BYTES>>>(bias, x, out);
}

// round 15
// speedup vs baseline: 1.1069x; 1.1069x over previous
#include <cuda_runtime.h>
#include <cuda_fp16.h>
#include <math.h>
#include <stdint.h>

#define U   1024
#define Bsz 64
#define T   128
#define Dd  256
#define N5  (5*U)        // 5120
#define N3  (3*U)        // 3072
#define KTOT (Dd + 2*U)  // 2304

#define NCTA   120                     // co-resident grid (<=148 SMs, 1 CTA/SM)
#define NTHR   512                     // 16 warps/CTA
#define NWARP  16
#define ZSPLIT 3
#define ZKLEN  (KTOT / ZSPLIT)   // 768
#define FSPLIT 12
#define FKLEN  (N3 / FSPLIT)     // 256
#define FCTAS  (U / 128 * FSPLIT)      // 96
#define NTILE  128
#define KCH    64                // K elems per chunk (128 B rows fp16)

// SMEM: rows padded to 144B -> conflict-free ldmatrix
#define ROWB   144
#define A_BLK  (64 * ROWB)             // 9216
#define B_BLK  (128 * ROWB)            // 18432
#define STG_BYTES (A_BLK + B_BLK)      // 27648
#define NSTG   4
#define GSMEM_BYTES (NSTG * STG_BYTES) // 110592

// ---------------- static device scratch --------------------------------------
__device__ __align__(128) __half g_Wt [(size_t)N5 * KTOT];  // W^T fp16 [n][k]
__device__ __align__(128) __half g_AGt[(size_t)U * N3];     // agg^T fp16 [n][k]
__device__ __align__(128) __half g_A16[Bsz * KTOT];         // [x|h|c] fp16
__device__ __align__(128) __half g_O16[Bsz * N3];           // O fp16
__device__ __align__(128) float g_c  [Bsz * U];
__device__ __align__(128) float g_zp [ZSPLIT * Bsz * N5];
__device__ __align__(128) float g_fp [FSPLIT * Bsz * U];
__device__ float g_s[6];
__device__ unsigned g_barA[T];
__device__ unsigned g_barB[T];
__device__ unsigned g_barC[T];
__device__ unsigned g_barD[T];

// ---------------- helpers -----------------------------------------------------
__device__ __forceinline__ float sigf(float x) { return 1.f / (1.f + expf(-x)); }

__device__ __forceinline__ uint32_t smem_u32(const void* p) {
    uint32_t a;
    asm("{ .reg .u64 t; cvta.to.shared.u64 t, %1; cvt.u32.u64 %0, t; }" : "=r"(a) : "l"(p));
    return a;
}
__device__ __forceinline__ void cpasync16(uint32_t s, const void* g) {
    asm volatile("cp.async.cg.shared.global [%0], [%1], 16;" :: "r"(s), "l"(g) : "memory");
}
__device__ __forceinline__ void cp_commit() { asm volatile("cp.async.commit_group;" ::: "memory"); }
template<int N> __device__ __forceinline__ void cp_wait() {
    asm volatile("cp.async.wait_group %0;" :: "n"(N) : "memory");
}
__device__ __forceinline__ void ldsm4(uint32_t* d, uint32_t addr) {
    asm volatile("ldmatrix.sync.aligned.m8n8.x4.shared.b16 {%0,%1,%2,%3}, [%4];"
                 : "=r"(d[0]), "=r"(d[1]), "=r"(d[2]), "=r"(d[3]) : "r"(addr));
}
__device__ __forceinline__ void mma16816(float* c, const uint32_t* a, const uint32_t* b) {
    asm volatile("mma.sync.aligned.m16n8k16.row.col.f32.f16.f16.f32 "
                 "{%0,%1,%2,%3}, {%4,%5,%6,%7}, {%8,%9}, {%0,%1,%2,%3};"
                 : "+f"(c[0]), "+f"(c[1]), "+f"(c[2]), "+f"(c[3])
                 : "r"(a[0]), "r"(a[1]), "r"(a[2]), "r"(a[3]), "r"(b[0]), "r"(b[1]));
}
__device__ __forceinline__ void red_release_add(unsigned* p, unsigned v) {
    asm volatile("red.release.gpu.global.add.u32 [%0], %1;" :: "l"(p), "r"(v) : "memory");
}
__device__ __forceinline__ unsigned ld_acquire(const unsigned* p) {
    unsigned v;
    asm volatile("ld.acquire.gpu.global.u32 %0, [%1];" : "=r"(v) : "l"(p) : "memory");
    return v;
}
__device__ __forceinline__ float2 ldcg2(const float* p) {
    float2 v;
    asm volatile("ld.global.cg.v2.f32 {%0,%1}, [%2];" : "=f"(v.x), "=f"(v.y) : "l"(p));
    return v;
}
__device__ __forceinline__ void gbarN(unsigned* ctr, int tid, unsigned target) {
    __syncthreads();
    if (tid == 0) {
        red_release_add(ctr, 1u);
        while (ld_acquire(ctr) < target) __nanosleep(32);
    }
    __syncthreads();
}

// ---------------- block reduce helpers (16 warps) ------------------------------
__device__ __forceinline__ float blk_reduce_max(float v, float* sm) {
    #pragma unroll
    for (int o = 16; o; o >>= 1) v = fmaxf(v, __shfl_xor_sync(0xffffffffu, v, o));
    int w = threadIdx.x >> 5;
    if ((threadIdx.x & 31) == 0) sm[w] = v;
    __syncthreads();
    float r = sm[0];
    #pragma unroll
    for (int i = 1; i < NWARP; i++) r = fmaxf(r, sm[i]);
    __syncthreads();
    return r;
}
__device__ __forceinline__ float blk_reduce_sum(float v, float* sm) {
    #pragma unroll
    for (int o = 16; o; o >>= 1) v += __shfl_xor_sync(0xffffffffu, v, o);
    int w = threadIdx.x >> 5;
    if ((threadIdx.x & 31) == 0) sm[w] = v;
    __syncthreads();
    float r = sm[0];
    #pragma unroll
    for (int i = 1; i < NWARP; i++) r += sm[i];
    __syncthreads();
    return r;
}
struct ScanRes { float excl; float total; };
__device__ __forceinline__ ScanRes blk_scan(float s, float* sm) {
    float ws = s;
    #pragma unroll
    for (int o = 1; o < 32; o <<= 1) {
        float t = __shfl_up_sync(0xffffffffu, ws, o);
        if ((threadIdx.x & 31) >= o) ws += t;
    }
    int w = threadIdx.x >> 5;
    if ((threadIdx.x & 31) == 31) sm[w] = ws;
    __syncthreads();
    float warpBase = 0.f, run = 0.f;
    #pragma unroll
    for (int i = 0; i < NWARP; i++) { float t = sm[i]; if (i == w) warpBase = run; run += t; }
    __syncthreads();
    ScanRes r; r.excl = warpBase + (ws - s); r.total = run; return r;
}

// ---------------- init kernels (256 threads, 8-warp reductions) -----------------
__device__ __forceinline__ float blk_reduce_sum8(float v, float* sm) {
    #pragma unroll
    for (int o = 16; o; o >>= 1) v += __shfl_xor_sync(0xffffffffu, v, o);
    int w = threadIdx.x >> 5;
    if ((threadIdx.x & 31) == 0) sm[w] = v;
    __syncthreads();
    float r = sm[0];
    #pragma unroll
    for (int i = 1; i < 8; i++) r += sm[i];
    __syncthreads();
    return r;
}

__global__ void ktrans_W(const float* __restrict__ k1, const float* __restrict__ k2,
                         const float* __restrict__ k3) {
    __shared__ float tile[32][33];
    int kt = blockIdx.x * 32, nt = blockIdx.y * 32;
    int tx = threadIdx.x, ty = threadIdx.y;
    #pragma unroll
    for (int i = 0; i < 32; i += 8) {
        int k = kt + ty + i, n = nt + tx;
        const float* src; int kr;
        if (k < Dd) { src = k1; kr = k; }
        else if (k < Dd + U) { src = k2; kr = k - Dd; }
        else { src = k3; kr = k - Dd - U; }
        tile[ty + i][tx] = src[(size_t)kr * N5 + n];
    }
    __syncthreads();
    #pragma unroll
    for (int i = 0; i < 32; i += 8) {
        int n = nt + ty + i, k = kt + tx;
        g_Wt[(size_t)n * KTOT + k] = __float2half(tile[tx][ty + i]);
    }
}
__global__ void ktrans_AG(const float* __restrict__ agg) {
    __shared__ float tile[32][33];
    int kt = blockIdx.x * 32, nt = blockIdx.y * 32;
    int tx = threadIdx.x, ty = threadIdx.y;
    #pragma unroll
    for (int i = 0; i < 32; i += 8)
        tile[ty + i][tx] = agg[(size_t)(kt + ty + i) * U + nt + tx];
    __syncthreads();
    #pragma unroll
    for (int i = 0; i < 32; i += 8) {
        int n = nt + ty + i, k = kt + tx;
        g_AGt[(size_t)n * N3 + k] = __float2half(tile[tx][ty + i]);
    }
}

__global__ void kinit_all(const float* __restrict__ x,
                          const float* a0, const float* b0, const float* a1, const float* b1,
                          const float* a2, const float* b2, const float* a3, const float* b3,
                          const float* a4, const float* b4, const float* a5, const float* b5) {
    __shared__ float sm[8];
    int b = blockIdx.x;
    if (b == 0) {
        const float* as[6] = {a0, a1, a2, a3, a4, a5};
        const float* bs[6] = {b0, b1, b2, b3, b4, b5};
        for (int p = 0; p < 6; p++) {
            float s = 0.f;
            for (int i = threadIdx.x; i < U; i += 256) s += as[p][i] * bs[p][i];
            float tot = blk_reduce_sum8(s, sm);
            if (threadIdx.x == 0) g_s[p] = tot;
            __syncthreads();
        }
        if (threadIdx.x < T) {
            g_barA[threadIdx.x] = 0u;
            g_barB[threadIdx.x] = 0u;
            g_barC[threadIdx.x] = 0u;
            g_barD[threadIdx.x] = 0u;
        }
    }
    for (int i = threadIdx.x; i < KTOT; i += 256)
        g_A16[b * KTOT + i] = __float2half((i < Dd) ? x[(size_t)(b * T) * Dd + i] : 0.f);
    for (int i = threadIdx.x; i < U; i += 256) g_c[b * U + i] = 0.f;
}

// ---------------- GEMM body: 16 warps, warp tile 16x32 --------------------------
// MODE 0: z (LDK=2304, KLEN=768, +bias ks0) | MODE 1: f (LDK=3072, KLEN=256)
template<int MODE>
__device__ __forceinline__ void gemm_body(uint32_t smb, int tid, int n0, int ks,
                                          const float* __restrict__ bias) {
    constexpr int LDK  = (MODE == 0) ? KTOT : N3;
    constexpr int NTOT = (MODE == 0) ? N5 : U;
    constexpr int KLEN = (MODE == 0) ? ZKLEN : FKLEN;
    constexpr int NC   = KLEN / KCH;

    const __half* Wp = (MODE == 0) ? g_Wt : g_AGt;
    const __half* Ap = (MODE == 0) ? g_A16 : g_O16;
    float* OUT = (MODE == 0) ? g_zp : g_fp;

    const int kbase = ks * KLEN;
    const int lane  = tid & 31;
    const int w     = tid >> 5;

    // 1536 x 16B segs per chunk over 512 threads -> 3 each
    const __half* srcB[3];
    uint32_t dstO[3];
    #pragma unroll
    for (int i = 0; i < 3; i++) {
        int seg = tid + i * NTHR;
        if (seg < 512) {
            int r = seg >> 3, s = seg & 7;
            srcB[i] = Ap + (size_t)r * LDK + s * 8;
            dstO[i] = r * ROWB + s * 16;
        } else {
            int idx = seg - 512;
            int r = idx >> 3, s = idx & 7;
            srcB[i] = Wp + (size_t)(n0 + r) * LDK + s * 8;
            dstO[i] = A_BLK + r * ROWB + s * 16;
        }
    }
    auto load_chunk = [&](int kk, int stg) {
        const uint32_t bb = smb + stg * STG_BYTES;
        #pragma unroll
        for (int i = 0; i < 3; i++)
            cpasync16(bb + dstO[i], srcB[i] + kk);
        cp_commit();
    };

    // warp grid: 4 (M, 16 rows each) x 4 (N, 32 cols each)
    const int mrow0 = (w & 3) * 16;
    const int nrow0 = (w >> 2) * 32;
    const int rA  = mrow0 + (lane & 15);
    const int scA = lane >> 4;
    const int rB  = nrow0 + ((lane >> 4) << 3) + (lane & 7);
    const int scB = (lane >> 3) & 1;

    float acc[4][4] = {};

    #pragma unroll
    for (int p = 0; p < 3; p++)
        if (p < NC) load_chunk(kbase + p * KCH, p);

    for (int c = 0; c < NC; c++) {
        int rem = NC - 1 - c;
        if (rem >= 2) cp_wait<2>(); else if (rem == 1) cp_wait<1>(); else cp_wait<0>();
        __syncthreads();
        if (c + 3 < NC) load_chunk(kbase + (c + 3) * KCH, (c + 3) % NSTG);

        const uint32_t bb = smb + (c % NSTG) * STG_BYTES;
        #pragma unroll
        for (int s16 = 0; s16 < 4; s16++) {
            const int kd = s16 * 2;
            uint32_t ah[4], bh[2][4];
            ldsm4(ah, bb + rA * ROWB + (kd + scA) * 16);
            #pragma unroll
            for (int nj = 0; nj < 2; nj++)
                ldsm4(bh[nj], bb + A_BLK + (rB + nj * 16) * ROWB + (kd + scB) * 16);
            #pragma unroll
            for (int nf = 0; nf < 4; nf++)
                mma16816(acc[nf], ah, &bh[nf >> 1][(nf & 1) * 2]);
        }
    }

    #pragma unroll
    for (int nf = 0; nf < 4; nf++) {
        int row = mrow0 + (lane >> 2);
        int col = n0 + nrow0 + nf * 8 + (lane & 3) * 2;
        float2 v0 = make_float2(acc[nf][0], acc[nf][1]);
        float2 v1 = make_float2(acc[nf][2], acc[nf][3]);
        if (MODE == 0 && ks == 0) {
            v0.x += bias[col]; v0.y += bias[col + 1];
            v1.x += bias[col]; v1.y += bias[col + 1];
        }
        *reinterpret_cast<float2*>(OUT + (size_t)(ks * Bsz + row) * NTOT + col) = v0;
        *reinterpret_cast<float2*>(OUT + (size_t)(ks * Bsz + row + 8) * NTOT + col) = v1;
    }
}

// ---------------- gate body (512 threads, 2 elems each) -------------------------
__device__ __forceinline__ void gate_body(int b, int tid) {
    __shared__ float sm[NWARP];
    const int i0 = tid * 2;

    float uz[2], dz[2], rz[2];
    {
        #define LOAD3(off, out) {                                                   \
            float2 s0 = ldcg2(g_zp + (size_t)(0*Bsz+b)*N5 + (off));                    \
            float2 s1 = ldcg2(g_zp + (size_t)(1*Bsz+b)*N5 + (off));                    \
            float2 s2 = ldcg2(g_zp + (size_t)(2*Bsz+b)*N5 + (off));                    \
            out[0] = s0.x + s1.x + s2.x; out[1] = s0.y + s1.y + s2.y; }
        LOAD3(i0,         uz)
        LOAD3(U + i0,     dz)
        LOAD3(2 * U + i0, rz)
        #undef LOAD3
    }

    float mx = blk_reduce_max(fmaxf(uz[0], uz[1]), sm);
    float e[2];
    e[0] = expf(uz[0] - mx); e[1] = expf(uz[1] - mx);
    ScanRes s1 = blk_scan(e[0] + e[1], sm);
    float up[2];
    { float P = s1.excl, inv = 1.f / s1.total;
      P += e[0]; up[0] = P * inv;
      P += e[1]; up[1] = P * inv; }

    float mx2 = blk_reduce_max(fmaxf(dz[0], dz[1]), sm);
    float ed[2];
    ed[0] = expf(dz[0] - mx2); ed[1] = expf(dz[1] - mx2);
    ScanRes s2 = blk_scan(ed[0] + ed[1], sm);
    float dn[2];
    { float P = s2.excl, inv = 1.f / s2.total;
      P += ed[0]; dn[0] = (s2.total - P + ed[0]) * inv;
      P += ed[1]; dn[1] = (s2.total - P + ed[1]) * inv; }

    float pdu = dn[0] * up[0] + dn[1] * up[1];
    float pru = rz[0] * up[0] + rz[1] * up[1];
    float pdr = dn[0] * rz[0] + dn[1] * rz[1];
    float du = blk_reduce_sum(pdu, sm);
    float ru = blk_reduce_sum(pru, sm);
    float dr = blk_reduce_sum(pdr, sm);

    const float s_ud = g_s[0], s_ur = g_s[1], s_ru = g_s[2];
    const float s_rd = g_s[3], s_du = g_s[4], s_dr = g_s[5];

    #pragma unroll
    for (int l = 0; l < 2; l++) {
        float t1 = sigf(s_ud * up[l] * du) + sigf(s_ur * up[l] * ru);
        float t2 = sigf(s_ru * rz[l] * ru) + sigf(s_rd * rz[l] * dr);
        float t3 = sigf(s_du * dn[l] * du) + sigf(s_dr * dn[l] * dr);
        g_O16[b * N3 + i0 + l]         = __float2half(t1);
        g_O16[b * N3 + U + i0 + l]     = __float2half(t2);
        g_O16[b * N3 + 2 * U + i0 + l] = __float2half(t3);
    }
}

// ---------------- update body (512 threads, 2 elems each) -----------------------
__device__ __forceinline__ void update_body(int b, int tid, int t,
                                            const float* __restrict__ x,
                                            float* __restrict__ out) {
    const int j = tid * 2;
    float fs0 = 0.f, fs1 = 0.f;
    #pragma unroll
    for (int ks = 0; ks < FSPLIT; ks++) {
        float2 p = ldcg2(g_fp + (size_t)(ks * Bsz + b) * U + j);
        fs0 += p.x; fs1 += p.y;
    }
    float og0 = 0.f, og1 = 0.f, zc0 = 0.f, zc1 = 0.f;
    #pragma unroll
    for (int ks = 0; ks < ZSPLIT; ks++) {
        float2 p = ldcg2(g_zp + (size_t)(ks * Bsz + b) * N5 + 3 * U + j);
        og0 += p.x; og1 += p.y;
        p = ldcg2(g_zp + (size_t)(ks * Bsz + b) * N5 + 4 * U + j);
        zc0 += p.x; zc1 += p.y;
    }
    float fv[2] = {fs0, fs1}, ov[2] = {og0, og1}, zv[2] = {zc0, zc1};
    #pragma unroll
    for (int l = 0; l < 2; l++) {
        float f  = sigf(fv[l]);
        float ci = tanhf(zv[l]);
        float co = g_c[(size_t)b * U + j + l];
        float cn = f * co + (1.f - f) * ci;
        float hn = ov[l] * tanhf(cn);
        g_c[(size_t)b * U + j + l] = cn;
        out[((size_t)b * T + t) * U + j + l] = hn;
        g_A16[b * KTOT + Dd + j + l]     = __float2half(hn);
        g_A16[b * KTOT + Dd + U + j + l] = __float2half(cn);
    }
    if (t + 1 < T && tid < 128) {
        #pragma unroll
        for (int l = 0; l < 2; l++) {
            int d = tid * 2 + l;
            g_A16[b * KTOT + d] = __float2half(x[((size_t)b * T + (t + 1)) * Dd + d]);
        }
    }
}

// ---------------- persistent scan kernel: 120 CTAs x 512 thr --------------------
__global__ void __launch_bounds__(NTHR) k_scan(const float* __restrict__ bias,
                                               const float* __restrict__ x,
                                               float* __restrict__ out) {
    const int bid = blockIdx.x, tid = threadIdx.x;
    extern __shared__ char dyn[];
    const uint32_t smb = smem_u32(dyn);

    const int n0z = (bid % 40) * NTILE, ksz = bid / 40;
    const int n0f = (bid % 8) * NTILE,  ksf = bid / 8;

    for (int t = 0; t < T; t++) {
        gemm_body<0>(smb, tid, n0z, ksz, bias);
        gbarN(&g_barA[t], tid, NCTA);

        if (bid < FCTAS) {
            if (bid < Bsz) gate_body(bid, tid);
            gbarN(&g_barB[t], tid, FCTAS);
            gemm_body<1>(smb, tid, n0f, ksf, nullptr);
            gbarN(&g_barC[t], tid, FCTAS);
            if (bid < Bsz) update_body(bid, tid, t, x, out);
        }
        gbarN(&g_barD[t], tid, NCTA);
    }
}

// ---------------- launch ---------------------------------------------------------
extern "C" void kernel_launch(void* const* d_in, const int* in_sizes, int n_in,
                              void* d_out, int out_size) {
    const float* x    = (const float*)d_in[0];
    const float* kern = (const float*)d_in[1];
    const float* rker = (const float*)d_in[2];
    const float* cker = (const float*)d_in[3];
    const float* bias = (const float*)d_in[4];
    const float* agg  = (const float*)d_in[5];
    float* out = (float*)d_out;

    cudaFuncSetAttribute(k_scan, cudaFuncAttributeMaxDynamicSharedMemorySize, GSMEM_BYTES);

    ktrans_W <<<dim3(KTOT / 32, N5 / 32), dim3(32, 8)>>>(kern, rker, cker);
    ktrans_AG<<<dim3(N3 / 32,  U  / 32), dim3(32, 8)>>>(agg);
    kinit_all<<<Bsz, 256>>>(x,
                            (const float*)d_in[6],  (const float*)d_in[7],
                            (const float*)d_in[8],  (const float*)d_in[9],
                            (const float*)d_in[10], (const float*)d_in[11],
                            (const float*)d_in[12], (const float*)d_in[13],
                            (const float*)d_in[14], (const float*)d_in[15],
                            (const float*)d_in[16], (const float*)d_in[17]);

    k_scan<<<NCTA, NTHR, GSMEM_BYTES>>>(bias, x, out);
}